// round 13
// baseline (speedup 1.0000x reference)
#include <cuda_runtime.h>
#include <cuda_fp16.h>

#define NN   100000
#define FIN  256
#define HDIM 128
#define CDIM 64
#define MAXE 1600000
#define NCSR 148                  // scan-pipeline blocks (co-resident wave 1)
#define GB1  ((NN + 127) / 128)   // gemm1 tiles = 782
#define CB   391                  // histogram blocks in mega
#define ZB   128                  // tail-zero blocks in mega
#define ZD   ((NN + 255) / 256)   // deg-zero blocks appended to score

// Scratch (static device globals — allocation-free per harness rules)
__device__ int     g_degi[NN];              // zeroed at END of each call (k_score)
__device__ int     g_rowptr[NN + 1];
__device__ int     g_bsum[NCSR];
__device__ int     g_boff[NCSR];
__device__ int     g_cursor[NN];
__device__ int     g_esrc[MAXE];            // edge sources grouped by dst (CSR)
__device__ float   g_dis[NN];
__device__ __half2 g_hw1h[NN * HDIM / 2];   // fp16: (x@W1)[v]  (UNSCALED)
__device__ float   g_agg1[NN * HDIM];       // fp32: relu(layer-1 aggregate)
__device__ __half2 g_hw2h[NN * CDIM / 2];   // fp16: dis[v]*(agg1@W2)[v]
__device__ __half2 g_agg2h[NN * CDIM / 2];  // fp16: final h2
__device__ int     g_barc;                  // barrier arrive counter
__device__ int     g_barg;                  // barrier generation

__device__ __forceinline__ unsigned f2tf32(float f) {
    unsigned u;
    asm("cvt.rna.tf32.f32 %0, %1;\n" : "=r"(u) : "f"(f));
    return u;
}

__device__ __forceinline__ void mma_tf32(float* d, const unsigned* a, const unsigned* b) {
    asm volatile(
        "mma.sync.aligned.m16n8k8.row.col.f32.tf32.tf32.f32 "
        "{%0,%1,%2,%3}, {%4,%5,%6,%7}, {%8,%9}, {%0,%1,%2,%3};\n"
        : "+f"(d[0]), "+f"(d[1]), "+f"(d[2]), "+f"(d[3])
        : "r"(a[0]), "r"(a[1]), "r"(a[2]), "r"(a[3]), "r"(b[0]), "r"(b[1]));
}

__device__ __forceinline__ void u4_to_f8(uint4 u, float* f) {
    float2 t;
    t = __half22float2(*(__half2*)&u.x); f[0] = t.x; f[1] = t.y;
    t = __half22float2(*(__half2*)&u.y); f[2] = t.x; f[3] = t.y;
    t = __half22float2(*(__half2*)&u.z); f[4] = t.x; f[5] = t.y;
    t = __half22float2(*(__half2*)&u.w); f[6] = t.x; f[7] = t.y;
}

// Grid barrier among NCSR co-resident blocks.
__device__ __forceinline__ void csr_barrier() {
    __syncthreads();
    if (threadIdx.x == 0) {
        int gen = atomicAdd(&g_barg, 0);
        __threadfence();
        int t = atomicAdd(&g_barc, 1);
        if (t == NCSR - 1) {
            atomicExch(&g_barc, 0);
            __threadfence();
            atomicAdd(&g_barg, 1);
        } else {
            while (atomicAdd(&g_barg, 0) == gen) { __nanosleep(64); }
        }
    }
    __syncthreads();
}

// ───────────────────────── TF32 tensor-core GEMM body ─────────────────────────
// tf32 conversion hoisted to the STS side: smem tiles hold tf32 bit patterns,
// the compute loop is pure LDS + MMA (no cvt in the hot loop).
// SCALE_DIS ? C = fp16(dis[row]*(A@B)) : C = fp16(A@B).
// NOTE: g_* pointers must be resolved in DEVICE code (host shadow-symbol trap).
template<int BM, int BN, int BK, int WM, int WN, int NT, bool SCALE_DIS>
__device__ __forceinline__ void mma_body(
    int bx, const float* __restrict__ A, const float* __restrict__ Bg,
    __half2* __restrict__ C, int M, int N, int K)
{
    constexpr int BKp = BK + 4;
    constexpr int BNp = BN + 8;
    __shared__ unsigned As[2][BM][BKp];
    __shared__ unsigned Bs[2][BK][BNp];

    const int tid  = threadIdx.x;
    const int wid  = tid >> 5;
    const int lane = tid & 31;
    const int grp  = lane >> 2;
    const int qi   = lane & 3;
    constexpr int NWN = BN / WN;
    const int warp_m = wid / NWN;
    const int warp_n = wid % NWN;
    constexpr int MF = WM / 16;
    constexpr int NF = WN / 8;

    const int brow = bx * BM;

    float acc[MF][NF][4];
    #pragma unroll
    for (int i = 0; i < MF; i++)
        #pragma unroll
        for (int j = 0; j < NF; j++)
            #pragma unroll
            for (int q = 0; q < 4; q++) acc[i][j][q] = 0.0f;

    constexpr int AIT = (BM * BK / 4) / NT;
    constexpr int BIT = (BK * BN / 4) / NT;

    float4 areg[AIT], breg[BIT];

    auto ldgA = [&](int k0) {
        #pragma unroll
        for (int it = 0; it < AIT; it++) {
            int idx  = tid + it * NT;
            int row  = idx / (BK / 4);
            int kc   = (idx % (BK / 4)) * 4;
            int grow = brow + row;
            if (grow > M - 1) grow = M - 1;   // clamp: rows >= M never stored
            areg[it] = *(const float4*)(A + (long long)grow * K + k0 + kc);
        }
    };
    auto ldgB = [&](int k0) {
        #pragma unroll
        for (int it = 0; it < BIT; it++) {
            int idx = tid + it * NT;
            int kk  = idx / (BN / 4);
            int nc  = (idx % (BN / 4)) * 4;
            breg[it] = *(const float4*)(Bg + (long long)(k0 + kk) * N + nc);
        }
    };
    auto stsA = [&](int buf) {
        #pragma unroll
        for (int it = 0; it < AIT; it++) {
            int idx = tid + it * NT;
            int row = idx / (BK / 4);
            int kc  = (idx % (BK / 4)) * 4;
            *(uint4*)&As[buf][row][kc] = make_uint4(
                f2tf32(areg[it].x), f2tf32(areg[it].y),
                f2tf32(areg[it].z), f2tf32(areg[it].w));
        }
    };
    auto stsB = [&](int buf) {
        #pragma unroll
        for (int it = 0; it < BIT; it++) {
            int idx = tid + it * NT;
            int kk  = idx / (BN / 4);
            int nc  = (idx % (BN / 4)) * 4;
            *(uint4*)&Bs[buf][kk][nc] = make_uint4(
                f2tf32(breg[it].x), f2tf32(breg[it].y),
                f2tf32(breg[it].z), f2tf32(breg[it].w));
        }
    };
    auto compute = [&](int buf) {
        #pragma unroll
        for (int ks = 0; ks < BK / 8; ks++) {
            int kk = ks * 8;
            unsigned a[MF][4], b[NF][2];
            #pragma unroll
            for (int fm = 0; fm < MF; fm++) {
                const unsigned* ap = &As[buf][warp_m * WM + fm * 16 + grp][kk + qi];
                a[fm][0] = ap[0];
                a[fm][1] = ap[8 * BKp];
                a[fm][2] = ap[4];
                a[fm][3] = ap[8 * BKp + 4];
            }
            #pragma unroll
            for (int fn = 0; fn < NF; fn++) {
                const unsigned* bp = &Bs[buf][kk + qi][warp_n * WN + fn * 8 + grp];
                b[fn][0] = bp[0];
                b[fn][1] = bp[4 * BNp];
            }
            #pragma unroll
            for (int fm = 0; fm < MF; fm++)
                #pragma unroll
                for (int fn = 0; fn < NF; fn++)
                    mma_tf32(acc[fm][fn], a[fm], b[fn]);
        }
    };

    // Prologue
    ldgA(0); ldgB(0);
    stsA(0); stsB(0);
    __syncthreads();

    const int KT = K / BK;
    for (int t = 1; t < KT; t++) {
        ldgA(t * BK); ldgB(t * BK);   // global loads overlap compute below
        compute((t - 1) & 1);
        stsA(t & 1); stsB(t & 1);
        __syncthreads();
    }
    compute((KT - 1) & 1);

    #pragma unroll
    for (int fm = 0; fm < MF; fm++) {
        int r0 = brow + warp_m * WM + fm * 16 + grp;
        int r1 = r0 + 8;
        float d0 = 1.0f, d1 = 1.0f;
        if (SCALE_DIS) {
            d0 = (r0 < M) ? g_dis[r0] : 0.0f;
            d1 = (r1 < M) ? g_dis[r1] : 0.0f;
        }
        #pragma unroll
        for (int fn = 0; fn < NF; fn++) {
            int col = warp_n * WN + fn * 8 + 2 * qi;
            if (r0 < M)
                C[((long long)r0 * N + col) >> 1] =
                    __floats2half2_rn(acc[fm][fn][0] * d0, acc[fm][fn][1] * d0);
            if (r1 < M)
                C[((long long)r1 * N + col) >> 1] =
                    __floats2half2_rn(acc[fm][fn][2] * d1, acc[fm][fn][3] * d1);
        }
    }
}

// ───────────────────────── mega: gemm1 ∥ histogram ∥ tail-zero ─────────────────
// g_degi enters this kernel ZEROED (invariant maintained by k_score's tail).
__global__ void __launch_bounds__(256)
k_mega(const float* __restrict__ x, const float* __restrict__ W1,
       const int* __restrict__ dst, int E,
       float* __restrict__ out, int SE, int total)
{
    int bx = blockIdx.x;
    if (bx < GB1) {   // gemm1: hw1h = fp16(x @ W1), unscaled
        mma_body<128, 128, 16, 64, 32, 256, false>(bx, x, W1, g_hw1h, NN, HDIM, FIN);
        return;
    }
    bx -= GB1;
    if (bx < CB) {    // degree histogram
        for (int e = bx * 256 + threadIdx.x; e < E; e += CB * 256)
            atomicAdd(&g_degi[dst[e]], 1);
        return;
    }
    bx -= CB;         // zero the tail of the output
    for (int i = SE + bx * 256 + threadIdx.x; i < total; i += ZB * 256)
        out[i] = 0.0f;
}

// ───────────────────────── fused 3-phase scan (148 blocks, grid barriers) ──────
__global__ void __launch_bounds__(256)
k_scan(int E)
{
    const int c   = blockIdx.x;
    const int tid = threadIdx.x;
    __shared__ int sc[256];
    const int chunk = (NN + NCSR - 1) / NCSR;
    const int lo = c * chunk;
    const int hi = (lo + chunk < NN) ? lo + chunk : NN;

    // Phase A: per-block chunk sums.
    {
        int s = 0;
        for (int i = lo + tid; i < hi; i += 256) s += g_degi[i];
        sc[tid] = s; __syncthreads();
        #pragma unroll
        for (int o = 128; o; o >>= 1) {
            if (tid < o) sc[tid] += sc[tid + o];
            __syncthreads();
        }
        if (tid == 0) g_bsum[c] = sc[0];
    }
    csr_barrier();

    // Phase B: block 0 exclusive-scans the chunk sums.
    if (c == 0) {
        int v = (tid < NCSR) ? g_bsum[tid] : 0;
        sc[tid] = v; __syncthreads();
        #pragma unroll
        for (int o = 1; o < 256; o <<= 1) {
            int t2 = (tid >= o) ? sc[tid - o] : 0;
            __syncthreads();
            sc[tid] += t2;
            __syncthreads();
        }
        if (tid < NCSR) g_boff[tid] = sc[tid] - v;
    }
    csr_barrier();

    // Phase C: rowptr / cursor / dis over the chunk.
    {
        int running = g_boff[c];
        for (int base = lo; base < hi; base += 256) {
            int i = base + tid;
            int d = (i < hi) ? g_degi[i] : 0;
            sc[tid] = d; __syncthreads();
            #pragma unroll
            for (int o = 1; o < 256; o <<= 1) {
                int t2 = (tid >= o) ? sc[tid - o] : 0;
                __syncthreads();
                sc[tid] += t2;
                __syncthreads();
            }
            if (i < hi) {
                int r = running + sc[tid] - d;
                g_rowptr[i] = r;
                g_cursor[i] = r;
                g_dis[i]    = rsqrtf((float)d + 1.0f);
            }
            running += sc[255];
            __syncthreads();
        }
        if (c == 0 && tid == 0) g_rowptr[NN] = E;
    }
}

__global__ void k_bin(const int* __restrict__ src, const int* __restrict__ dst, int E) {
    int e = blockIdx.x * blockDim.x + threadIdx.x;
    if (e >= E) return;
    int d = dst[e];
    int p = atomicAdd(&g_cursor[d], 1);
    g_esrc[p] = src[e];
}

// ───────────── gather aggregation: lean 32-reg bodies, 100% occupancy ──────────
// Layer 1: hw1h UNSCALED.  S = dv*h1[v] + Σ_e ds*h1[s];  agg1 = relu(dv*S + b1).
// 16 lanes per node, 1 uint4 per lane, 2-edge unroll, single accumulator set.
__global__ void __launch_bounds__(256, 8)
k_gather1(const float* __restrict__ b1) {
    int t = blockIdx.x * blockDim.x + threadIdx.x;
    int v = t >> 4, lane = t & 15;
    if (v >= NN) return;
    int beg = g_rowptr[v], end = g_rowptr[v + 1];
    float dv = g_dis[v];
    const uint4* hw = (const uint4*)g_hw1h;   // 16 uint4 per row

    float a[8];
    {
        float f[8];
        u4_to_f8(hw[(long long)v * 16 + lane], f);
        #pragma unroll
        for (int i = 0; i < 8; i++) a[i] = dv * f[i];
    }

    int p = beg;
    for (; p + 1 < end; p += 2) {
        int s0 = __ldg(&g_esrc[p]);
        int s1 = __ldg(&g_esrc[p + 1]);
        float d0 = g_dis[s0], d1 = g_dis[s1];
        uint4 u0 = hw[(long long)s0 * 16 + lane];
        uint4 u1 = hw[(long long)s1 * 16 + lane];
        float f0[8], f1[8];
        u4_to_f8(u0, f0); u4_to_f8(u1, f1);
        #pragma unroll
        for (int i = 0; i < 8; i++) a[i] = fmaf(d0, f0[i], a[i]);
        #pragma unroll
        for (int i = 0; i < 8; i++) a[i] = fmaf(d1, f1[i], a[i]);
    }
    if (p < end) {
        int s0 = __ldg(&g_esrc[p]);
        float d0 = g_dis[s0];
        float f0[8];
        u4_to_f8(hw[(long long)s0 * 16 + lane], f0);
        #pragma unroll
        for (int i = 0; i < 8; i++) a[i] = fmaf(d0, f0[i], a[i]);
    }
    float4 c0 = ((const float4*)b1)[lane * 2];
    float4 c1 = ((const float4*)b1)[lane * 2 + 1];
    float4* outp = (float4*)(g_agg1 + (long long)v * HDIM + lane * 8);
    outp[0] = make_float4(fmaxf(fmaf(dv, a[0], c0.x), 0.f),
                          fmaxf(fmaf(dv, a[1], c0.y), 0.f),
                          fmaxf(fmaf(dv, a[2], c0.z), 0.f),
                          fmaxf(fmaf(dv, a[3], c0.w), 0.f));
    outp[1] = make_float4(fmaxf(fmaf(dv, a[4], c1.x), 0.f),
                          fmaxf(fmaf(dv, a[5], c1.y), 0.f),
                          fmaxf(fmaf(dv, a[6], c1.z), 0.f),
                          fmaxf(fmaf(dv, a[7], c1.w), 0.f));
}

// Layer 2: hw2h pre-scaled by dis.  agg2 = fp16(dv*(hw2[v]+Σ hw2[s]) + b2).
// 8 lanes per node, 1 uint4 per lane, 2-edge unroll.
__global__ void __launch_bounds__(256, 8)
k_gather2(const float* __restrict__ b2) {
    int t = blockIdx.x * blockDim.x + threadIdx.x;
    int v = t >> 3, lane = t & 7;
    if (v >= NN) return;
    int beg = g_rowptr[v], end = g_rowptr[v + 1];
    float dv = g_dis[v];
    const uint4* hw = (const uint4*)g_hw2h;   // 8 uint4 per row

    float a[8];
    u4_to_f8(hw[(long long)v * 8 + lane], a);

    int p = beg;
    for (; p + 1 < end; p += 2) {
        int s0 = __ldg(&g_esrc[p]);
        int s1 = __ldg(&g_esrc[p + 1]);
        uint4 u0 = hw[(long long)s0 * 8 + lane];
        uint4 u1 = hw[(long long)s1 * 8 + lane];
        float f0[8], f1[8];
        u4_to_f8(u0, f0); u4_to_f8(u1, f1);
        #pragma unroll
        for (int i = 0; i < 8; i++) a[i] += f0[i] + f1[i];
    }
    if (p < end) {
        int s0 = __ldg(&g_esrc[p]);
        float f0[8];
        u4_to_f8(hw[(long long)s0 * 8 + lane], f0);
        #pragma unroll
        for (int i = 0; i < 8; i++) a[i] += f0[i];
    }
    float4 c0 = ((const float4*)b2)[lane * 2];
    float4 c1 = ((const float4*)b2)[lane * 2 + 1];
    uint4 u;
    *(__half2*)&u.x = __floats2half2_rn(fmaf(dv, a[0], c0.x), fmaf(dv, a[1], c0.y));
    *(__half2*)&u.y = __floats2half2_rn(fmaf(dv, a[2], c0.z), fmaf(dv, a[3], c0.w));
    *(__half2*)&u.z = __floats2half2_rn(fmaf(dv, a[4], c1.x), fmaf(dv, a[5], c1.y));
    *(__half2*)&u.w = __floats2half2_rn(fmaf(dv, a[6], c1.z), fmaf(dv, a[7], c1.w));
    ((uint4*)g_agg2h)[(long long)v * 8 + lane] = u;
}

// ──────── scoring (8 lanes/edge, 1 uint4 per side) + restore g_degi=0 ────────
__global__ void __launch_bounds__(256, 8)
k_score(const int* __restrict__ pos, const int* __restrict__ neg,
        int EPn, int SE, int sb, float* __restrict__ out)
{
    if ((int)blockIdx.x >= sb) {   // tail blocks: re-zero degree histogram
        int i = (blockIdx.x - sb) * 256 + threadIdx.x;
        if (i < NN) g_degi[i] = 0;
        return;
    }
    int t = blockIdx.x * blockDim.x + threadIdx.x;
    int e = t >> 3, lane = t & 7;
    if (e >= SE) return;
    int i, j;
    if (e < EPn) { j = pos[e];       i = pos[e + EPn]; }
    else         { j = neg[e - EPn]; i = neg[e];       }
    const uint4* h4 = (const uint4*)g_agg2h;
    uint4 ua = h4[(long long)i * 8 + lane];
    uint4 ub = h4[(long long)j * 8 + lane];
    float fa[8], fb[8];
    u4_to_f8(ua, fa);
    u4_to_f8(ub, fb);
    float s = 0.f;
    #pragma unroll
    for (int q = 0; q < 8; q++) s = fmaf(fa[q], fb[q], s);
    #pragma unroll
    for (int o = 4; o; o >>= 1) s += __shfl_xor_sync(0xffffffffu, s, o);
    if (lane == 0) out[e] = s;
}

// ───────────────────────── gemm2 wrapper ─────────────────────────
__global__ void __launch_bounds__(256)
k_gemm2(const float* __restrict__ W2)
{
    mma_body<128, 64, 16, 32, 32, 256, true>(blockIdx.x, g_agg1, W2, g_hw2h,
                                             NN, CDIM, HDIM);
}

extern "C" void kernel_launch(void* const* d_in, const int* in_sizes, int n_in,
                              void* d_out, int out_size)
{
    const float* x   = (const float*)d_in[0];
    // d_in[1] = masked_nodes (unused by the reference output)
    const int*   pos = (const int*)d_in[2];
    const int*   neg = (const int*)d_in[3];
    const int*   ei  = (const int*)d_in[4];
    const float* W1  = (const float*)d_in[5];
    const float* b1  = (const float*)d_in[6];
    const float* W2  = (const float*)d_in[7];
    const float* b2  = (const float*)d_in[8];
    float* out = (float*)d_out;

    const int E   = in_sizes[4] / 2;
    const int EPn = in_sizes[2] / 2;
    const int SE  = 2 * EPn;
    const int* src = ei;
    const int* dst = ei + E;

    // gemm1 ∥ degree histogram ∥ output-tail zeroing
    k_mega<<<GB1 + CB + ZB, 256>>>(x, W1, dst, E, out, SE, out_size);

    // fused 3-phase prefix scan (rowptr/cursor/dis)
    k_scan<<<NCSR, 256>>>(E);
    k_bin <<<(E + 255) / 256, 256>>>(src, dst, E);

    k_gather1<<<(NN * 16 + 255) / 256, 256>>>(b1);

    k_gemm2<<<(NN + 127) / 128, 256>>>(W2);
    k_gather2<<<(NN * 8 + 255) / 256, 256>>>(b2);

    const int sb = (SE * 8 + 255) / 256;
    k_score<<<sb + ZD, 256>>>(pos, neg, EPn, SE, sb, out);
}

// round 14
// speedup vs baseline: 1.0255x; 1.0255x over previous
#include <cuda_runtime.h>
#include <cuda_fp16.h>

#define NN   100000
#define FIN  256
#define HDIM 128
#define CDIM 64
#define MAXE 1600000
#define NCSR 148                  // CSR blocks in mega (co-resident wave 1)
#define GB1  ((NN + 127) / 128)   // gemm1 tiles = 782
#define CB   391                  // histogram blocks in pre
#define ZB   128                  // tail-zero blocks in pre
#define ZD   ((NN + 255) / 256)   // deg-zero blocks appended to score

// Scratch (static device globals — allocation-free per harness rules)
__device__ int     g_degi[NN];              // zeroed at END of each call (k_score)
__device__ int     g_rowptr[NN + 1];
__device__ int     g_bsum[NCSR];
__device__ int     g_boff[NCSR];
__device__ int     g_cursor[NN];
__device__ int     g_esrc[MAXE];            // edge sources grouped by dst (CSR)
__device__ float   g_dis[NN];
__device__ __half2 g_hw1h[NN * HDIM / 2];   // fp16: (x@W1)[v]  (UNSCALED)
__device__ float   g_agg1[NN * HDIM];       // fp32: relu(layer-1 aggregate)
__device__ __half2 g_hw2h[NN * CDIM / 2];   // fp16: dis[v]*(agg1@W2)[v]
__device__ __half2 g_agg2h[NN * CDIM / 2];  // fp16: final h2
__device__ int     g_barc;                  // barrier arrive counter
__device__ int     g_barg;                  // barrier generation

__device__ __forceinline__ void cp_async16(void* smem, const void* gmem) {
    unsigned s = (unsigned)__cvta_generic_to_shared(smem);
    asm volatile("cp.async.ca.shared.global [%0], [%1], 16;\n" :: "r"(s), "l"(gmem));
}
__device__ __forceinline__ void cp_commit() { asm volatile("cp.async.commit_group;\n"); }
__device__ __forceinline__ void cp_wait0()  { asm volatile("cp.async.wait_group 0;\n" ::: "memory"); }

__device__ __forceinline__ unsigned f2tf32(float f) {
    unsigned u;
    asm("cvt.rna.tf32.f32 %0, %1;\n" : "=r"(u) : "f"(f));
    return u;
}

__device__ __forceinline__ void mma_tf32(float* d, const unsigned* a, const unsigned* b) {
    asm volatile(
        "mma.sync.aligned.m16n8k8.row.col.f32.tf32.tf32.f32 "
        "{%0,%1,%2,%3}, {%4,%5,%6,%7}, {%8,%9}, {%0,%1,%2,%3};\n"
        : "+f"(d[0]), "+f"(d[1]), "+f"(d[2]), "+f"(d[3])
        : "r"(a[0]), "r"(a[1]), "r"(a[2]), "r"(a[3]), "r"(b[0]), "r"(b[1]));
}

__device__ __forceinline__ void u4_to_f8(uint4 u, float* f) {
    float2 t;
    t = __half22float2(*(__half2*)&u.x); f[0] = t.x; f[1] = t.y;
    t = __half22float2(*(__half2*)&u.y); f[2] = t.x; f[3] = t.y;
    t = __half22float2(*(__half2*)&u.z); f[4] = t.x; f[5] = t.y;
    t = __half22float2(*(__half2*)&u.w); f[6] = t.x; f[7] = t.y;
}

// Grid barrier among NCSR co-resident blocks.
__device__ __forceinline__ void csr_barrier() {
    __syncthreads();
    if (threadIdx.x == 0) {
        int gen = atomicAdd(&g_barg, 0);
        __threadfence();
        int t = atomicAdd(&g_barc, 1);
        if (t == NCSR - 1) {
            atomicExch(&g_barc, 0);
            __threadfence();
            atomicAdd(&g_barg, 1);
        } else {
            while (atomicAdd(&g_barg, 0) == gen) { __nanosleep(64); }
        }
    }
    __syncthreads();
}

// ───────────────────────── TF32 tensor-core GEMM body (R11 form) ───────────────
// SCALE_DIS ? C = fp16(dis[row]*(A@B)) : C = fp16(A@B).
// NOTE: g_* pointers must be resolved in DEVICE code (host shadow-symbol trap).
template<int BM, int BN, int BK, int WM, int WN, int NT, bool SCALE_DIS>
__device__ __forceinline__ void mma_body(
    int bx, const float* __restrict__ A, const float* __restrict__ Bg,
    __half2* __restrict__ C, int M, int N, int K)
{
    constexpr int BKp = BK + 4;
    constexpr int BNp = BN + 8;
    __shared__ float As[2][BM][BKp];
    __shared__ float Bs[2][BK][BNp];

    const int tid  = threadIdx.x;
    const int wid  = tid >> 5;
    const int lane = tid & 31;
    const int grp  = lane >> 2;
    const int qi   = lane & 3;
    constexpr int NWN = BN / WN;
    const int warp_m = wid / NWN;
    const int warp_n = wid % NWN;
    constexpr int MF = WM / 16;
    constexpr int NF = WN / 8;

    const int brow = bx * BM;

    float acc[MF][NF][4];
    #pragma unroll
    for (int i = 0; i < MF; i++)
        #pragma unroll
        for (int j = 0; j < NF; j++)
            #pragma unroll
            for (int q = 0; q < 4; q++) acc[i][j][q] = 0.0f;

    constexpr int AIT = (BM * BK / 4) / NT;
    constexpr int BIT = (BK * BN / 4) / NT;

    auto cpA = [&](int buf, int k0) {
        #pragma unroll
        for (int it = 0; it < AIT; it++) {
            int idx  = tid + it * NT;
            int row  = idx / (BK / 4);
            int kc   = (idx % (BK / 4)) * 4;
            int grow = brow + row;
            if (grow > M - 1) grow = M - 1;
            cp_async16(&As[buf][row][kc], A + (long long)grow * K + k0 + kc);
        }
    };
    auto cpB = [&](int buf, int k0) {
        #pragma unroll
        for (int it = 0; it < BIT; it++) {
            int idx = tid + it * NT;
            int kk  = idx / (BN / 4);
            int nc  = (idx % (BN / 4)) * 4;
            cp_async16(&Bs[buf][kk][nc], Bg + (long long)(k0 + kk) * N + nc);
        }
    };
    auto compute = [&](int buf) {
        #pragma unroll
        for (int ks = 0; ks < BK / 8; ks++) {
            int kk = ks * 8;
            unsigned a[MF][4], b[NF][2];
            #pragma unroll
            for (int fm = 0; fm < MF; fm++) {
                const float* ap = &As[buf][warp_m * WM + fm * 16 + grp][kk + qi];
                a[fm][0] = f2tf32(ap[0]);
                a[fm][1] = f2tf32(ap[8 * BKp]);
                a[fm][2] = f2tf32(ap[4]);
                a[fm][3] = f2tf32(ap[8 * BKp + 4]);
            }
            #pragma unroll
            for (int fn = 0; fn < NF; fn++) {
                const float* bp = &Bs[buf][kk + qi][warp_n * WN + fn * 8 + grp];
                b[fn][0] = f2tf32(bp[0]);
                b[fn][1] = f2tf32(bp[4 * BNp]);
            }
            #pragma unroll
            for (int fm = 0; fm < MF; fm++)
                #pragma unroll
                for (int fn = 0; fn < NF; fn++)
                    mma_tf32(acc[fm][fn], a[fm], b[fn]);
        }
    };

    cpA(0, 0); cpB(0, 0); cp_commit();
    cp_wait0(); __syncthreads();

    const int KT = K / BK;
    for (int t = 1; t < KT; t++) {
        cpA(t & 1, t * BK); cpB(t & 1, t * BK); cp_commit();
        compute((t - 1) & 1);
        cp_wait0(); __syncthreads();
    }
    compute((KT - 1) & 1);

    #pragma unroll
    for (int fm = 0; fm < MF; fm++) {
        int r0 = brow + warp_m * WM + fm * 16 + grp;
        int r1 = r0 + 8;
        float d0 = 1.0f, d1 = 1.0f;
        if (SCALE_DIS) {
            d0 = (r0 < M) ? g_dis[r0] : 0.0f;
            d1 = (r1 < M) ? g_dis[r1] : 0.0f;
        }
        #pragma unroll
        for (int fn = 0; fn < NF; fn++) {
            int col = warp_n * WN + fn * 8 + 2 * qi;
            if (r0 < M)
                C[((long long)r0 * N + col) >> 1] =
                    __floats2half2_rn(acc[fm][fn][0] * d0, acc[fm][fn][1] * d0);
            if (r1 < M)
                C[((long long)r1 * N + col) >> 1] =
                    __floats2half2_rn(acc[fm][fn][2] * d1, acc[fm][fn][3] * d1);
        }
    }
}

// ───────────────────────── pre: degree histogram ∥ output-tail zero ────────────
// g_degi enters this kernel ZEROED (invariant maintained by k_score's tail).
__global__ void __launch_bounds__(256)
k_pre(const int* __restrict__ dst, int E,
      float* __restrict__ out, int SE, int total)
{
    int bx = blockIdx.x;
    if (bx < CB) {    // degree histogram
        for (int e = bx * 256 + threadIdx.x; e < E; e += CB * 256)
            atomicAdd(&g_degi[dst[e]], 1);
        return;
    }
    bx -= CB;         // zero the tail of the output
    for (int i = SE + bx * 256 + threadIdx.x; i < total; i += ZB * 256)
        out[i] = 0.0f;
}

// ─────────── CSR blocks inside mega: 3-phase scan + bin (grid barriers) ────────
__device__ void csr_scan_bin(int c, const int* __restrict__ src,
                             const int* __restrict__ dst, int E)
{
    const int tid = threadIdx.x;
    __shared__ int sc[256];
    const int chunk = (NN + NCSR - 1) / NCSR;
    const int lo = c * chunk;
    const int hi = (lo + chunk < NN) ? lo + chunk : NN;

    // Phase A: per-block chunk sums.
    {
        int s = 0;
        for (int i = lo + tid; i < hi; i += 256) s += g_degi[i];
        sc[tid] = s; __syncthreads();
        #pragma unroll
        for (int o = 128; o; o >>= 1) {
            if (tid < o) sc[tid] += sc[tid + o];
            __syncthreads();
        }
        if (tid == 0) g_bsum[c] = sc[0];
    }
    csr_barrier();

    // Phase B: block 0 exclusive-scans the chunk sums.
    if (c == 0) {
        int v = (tid < NCSR) ? g_bsum[tid] : 0;
        sc[tid] = v; __syncthreads();
        #pragma unroll
        for (int o = 1; o < 256; o <<= 1) {
            int t2 = (tid >= o) ? sc[tid - o] : 0;
            __syncthreads();
            sc[tid] += t2;
            __syncthreads();
        }
        if (tid < NCSR) g_boff[tid] = sc[tid] - v;
    }
    csr_barrier();

    // Phase C: rowptr / cursor / dis over the chunk.
    {
        int running = g_boff[c];
        for (int base = lo; base < hi; base += 256) {
            int i = base + tid;
            int d = (i < hi) ? g_degi[i] : 0;
            sc[tid] = d; __syncthreads();
            #pragma unroll
            for (int o = 1; o < 256; o <<= 1) {
                int t2 = (tid >= o) ? sc[tid - o] : 0;
                __syncthreads();
                sc[tid] += t2;
                __syncthreads();
            }
            if (i < hi) {
                int r = running + sc[tid] - d;
                g_rowptr[i] = r;
                g_cursor[i] = r;
                g_dis[i]    = rsqrtf((float)d + 1.0f);
            }
            running += sc[255];
            __syncthreads();
        }
        if (c == 0 && tid == 0) g_rowptr[NN] = E;
    }
    csr_barrier();   // all cursors visible before any block bins

    // Phase D: bin edge sources by dst (grid-stride over CSR blocks).
    for (int e = c * 256 + tid; e < E; e += NCSR * 256) {
        int d = dst[e];
        int p = atomicAdd(&g_cursor[d], 1);
        g_esrc[p] = src[e];
    }
}

// ───────────────────────── mega: CSR pipeline ∥ gemm1 ─────────────────────────
__global__ void __launch_bounds__(256, 2)
k_mega(const float* __restrict__ x, const float* __restrict__ W1,
       const int* __restrict__ src, const int* __restrict__ dst, int E)
{
    if (blockIdx.x < NCSR) {
        csr_scan_bin(blockIdx.x, src, dst, E);
    } else {
        mma_body<128, 128, 16, 64, 32, 256, false>(
            blockIdx.x - NCSR, x, W1, g_hw1h, NN, HDIM, FIN);
    }
}

// ───────────── gather aggregation: 2 uint4 per lane (R11 form) ─────────────
// Layer 1: hw1h UNSCALED.  S = dv*h1[v] + Σ_e ds*h1[s];  agg1 = relu(dv*S + b1).
// 8 lanes per node; lane covers uint4 indices {lane, lane+8} of the 16-uint4 row.
__global__ void k_gather1(const float* __restrict__ b1) {
    int t = blockIdx.x * blockDim.x + threadIdx.x;
    int v = t >> 3, lane = t & 7;
    if (v >= NN) return;
    int beg = g_rowptr[v], end = g_rowptr[v + 1];
    float dv = g_dis[v];
    const uint4* hw = (const uint4*)g_hw1h;   // 16 uint4 per row

    float a[16];
    {
        uint4 u0 = hw[(long long)v * 16 + lane];
        uint4 u1 = hw[(long long)v * 16 + lane + 8];
        float f0[8], f1[8];
        u4_to_f8(u0, f0); u4_to_f8(u1, f1);
        #pragma unroll
        for (int i = 0; i < 8; i++) { a[i] = dv * f0[i]; a[8 + i] = dv * f1[i]; }
    }

    int p = beg;
    for (; p + 1 < end; p += 2) {
        int s0 = __ldg(&g_esrc[p]);
        int s1 = __ldg(&g_esrc[p + 1]);
        float d0 = g_dis[s0], d1 = g_dis[s1];
        uint4 u00 = hw[(long long)s0 * 16 + lane];
        uint4 u01 = hw[(long long)s0 * 16 + lane + 8];
        uint4 u10 = hw[(long long)s1 * 16 + lane];
        uint4 u11 = hw[(long long)s1 * 16 + lane + 8];
        float f00[8], f01[8], f10[8], f11[8];
        u4_to_f8(u00, f00); u4_to_f8(u01, f01);
        u4_to_f8(u10, f10); u4_to_f8(u11, f11);
        #pragma unroll
        for (int i = 0; i < 8; i++) {
            a[i]     = fmaf(d0, f00[i], a[i]);
            a[8 + i] = fmaf(d0, f01[i], a[8 + i]);
            a[i]     = fmaf(d1, f10[i], a[i]);
            a[8 + i] = fmaf(d1, f11[i], a[8 + i]);
        }
    }
    if (p < end) {
        int s0 = __ldg(&g_esrc[p]);
        float d0 = g_dis[s0];
        uint4 u00 = hw[(long long)s0 * 16 + lane];
        uint4 u01 = hw[(long long)s0 * 16 + lane + 8];
        float f00[8], f01[8];
        u4_to_f8(u00, f00); u4_to_f8(u01, f01);
        #pragma unroll
        for (int i = 0; i < 8; i++) {
            a[i]     = fmaf(d0, f00[i], a[i]);
            a[8 + i] = fmaf(d0, f01[i], a[8 + i]);
        }
    }

    const float4* bb = (const float4*)b1;
    float o[16];
    #pragma unroll
    for (int h = 0; h < 2; h++) {
        float4 c0 = bb[h * 16 + lane * 2];
        float4 c1 = bb[h * 16 + lane * 2 + 1];
        o[h*8+0] = fmaxf(fmaf(dv, a[h*8+0], c0.x), 0.f);
        o[h*8+1] = fmaxf(fmaf(dv, a[h*8+1], c0.y), 0.f);
        o[h*8+2] = fmaxf(fmaf(dv, a[h*8+2], c0.z), 0.f);
        o[h*8+3] = fmaxf(fmaf(dv, a[h*8+3], c0.w), 0.f);
        o[h*8+4] = fmaxf(fmaf(dv, a[h*8+4], c1.x), 0.f);
        o[h*8+5] = fmaxf(fmaf(dv, a[h*8+5], c1.y), 0.f);
        o[h*8+6] = fmaxf(fmaf(dv, a[h*8+6], c1.z), 0.f);
        o[h*8+7] = fmaxf(fmaf(dv, a[h*8+7], c1.w), 0.f);
        float4* outp = (float4*)(g_agg1 + (long long)v * HDIM + h * 64 + lane * 8);
        outp[0] = make_float4(o[h*8+0], o[h*8+1], o[h*8+2], o[h*8+3]);
        outp[1] = make_float4(o[h*8+4], o[h*8+5], o[h*8+6], o[h*8+7]);
    }
}

// Layer 2: hw2h pre-scaled by dis.  agg2 = fp16(dv*(hw2[v]+Σ hw2[s]) + b2).
// 4 lanes per node; lane covers uint4 indices {lane, lane+4} of the 8-uint4 row.
__global__ void k_gather2(const float* __restrict__ b2) {
    int t = blockIdx.x * blockDim.x + threadIdx.x;
    int v = t >> 2, lane = t & 3;
    if (v >= NN) return;
    int beg = g_rowptr[v], end = g_rowptr[v + 1];
    float dv = g_dis[v];
    const uint4* hw = (const uint4*)g_hw2h;   // 8 uint4 per row

    float a[16];
    {
        uint4 u0 = hw[(long long)v * 8 + lane];
        uint4 u1 = hw[(long long)v * 8 + lane + 4];
        float f0[8], f1[8];
        u4_to_f8(u0, f0); u4_to_f8(u1, f1);
        #pragma unroll
        for (int i = 0; i < 8; i++) { a[i] = f0[i]; a[8 + i] = f1[i]; }
    }

    int p = beg;
    for (; p + 1 < end; p += 2) {
        int s0 = __ldg(&g_esrc[p]);
        int s1 = __ldg(&g_esrc[p + 1]);
        uint4 u00 = hw[(long long)s0 * 8 + lane];
        uint4 u01 = hw[(long long)s0 * 8 + lane + 4];
        uint4 u10 = hw[(long long)s1 * 8 + lane];
        uint4 u11 = hw[(long long)s1 * 8 + lane + 4];
        float f00[8], f01[8], f10[8], f11[8];
        u4_to_f8(u00, f00); u4_to_f8(u01, f01);
        u4_to_f8(u10, f10); u4_to_f8(u11, f11);
        #pragma unroll
        for (int i = 0; i < 8; i++) {
            a[i]     += f00[i] + f10[i];
            a[8 + i] += f01[i] + f11[i];
        }
    }
    if (p < end) {
        int s0 = __ldg(&g_esrc[p]);
        uint4 u00 = hw[(long long)s0 * 8 + lane];
        uint4 u01 = hw[(long long)s0 * 8 + lane + 4];
        float f00[8], f01[8];
        u4_to_f8(u00, f00); u4_to_f8(u01, f01);
        #pragma unroll
        for (int i = 0; i < 8; i++) { a[i] += f00[i]; a[8 + i] += f01[i]; }
    }

    const float4* bb = (const float4*)b2;
    #pragma unroll
    for (int h = 0; h < 2; h++) {
        float4 c0 = bb[h * 8 + lane * 2];
        float4 c1 = bb[h * 8 + lane * 2 + 1];
        float o0 = fmaf(dv, a[h*8+0], c0.x);
        float o1 = fmaf(dv, a[h*8+1], c0.y);
        float o2 = fmaf(dv, a[h*8+2], c0.z);
        float o3 = fmaf(dv, a[h*8+3], c0.w);
        float o4 = fmaf(dv, a[h*8+4], c1.x);
        float o5 = fmaf(dv, a[h*8+5], c1.y);
        float o6 = fmaf(dv, a[h*8+6], c1.z);
        float o7 = fmaf(dv, a[h*8+7], c1.w);
        uint4 u;
        *(__half2*)&u.x = __floats2half2_rn(o0, o1);
        *(__half2*)&u.y = __floats2half2_rn(o2, o3);
        *(__half2*)&u.z = __floats2half2_rn(o4, o5);
        *(__half2*)&u.w = __floats2half2_rn(o6, o7);
        ((uint4*)g_agg2h)[(long long)v * 8 + h * 4 + lane] = u;
    }
}

// ──────── scoring (4 lanes/edge, 2 uint4 per side) + restore g_degi=0 ────────
__global__ void k_score(const int* __restrict__ pos, const int* __restrict__ neg,
                        int EPn, int SE, int sb, float* __restrict__ out)
{
    if ((int)blockIdx.x >= sb) {   // tail blocks: re-zero degree histogram
        int i = (blockIdx.x - sb) * 256 + threadIdx.x;
        if (i < NN) g_degi[i] = 0;
        return;
    }
    int t = blockIdx.x * blockDim.x + threadIdx.x;
    int e = t >> 2, lane = t & 3;
    if (e >= SE) return;
    int i, j;
    if (e < EPn) { j = pos[e];       i = pos[e + EPn]; }
    else         { j = neg[e - EPn]; i = neg[e];       }
    const uint4* h4 = (const uint4*)g_agg2h;
    uint4 ua0 = h4[(long long)i * 8 + lane];
    uint4 ua1 = h4[(long long)i * 8 + lane + 4];
    uint4 ub0 = h4[(long long)j * 8 + lane];
    uint4 ub1 = h4[(long long)j * 8 + lane + 4];
    float fa0[8], fa1[8], fb0[8], fb1[8];
    u4_to_f8(ua0, fa0); u4_to_f8(ua1, fa1);
    u4_to_f8(ub0, fb0); u4_to_f8(ub1, fb1);
    float s = 0.f;
    #pragma unroll
    for (int q = 0; q < 8; q++) s = fmaf(fa0[q], fb0[q], s);
    #pragma unroll
    for (int q = 0; q < 8; q++) s = fmaf(fa1[q], fb1[q], s);
    s += __shfl_xor_sync(0xffffffffu, s, 2);
    s += __shfl_xor_sync(0xffffffffu, s, 1);
    if (lane == 0) out[e] = s;
}

// ───────────────────────── gemm2 wrapper ─────────────────────────
__global__ void __launch_bounds__(256)
k_gemm2(const float* __restrict__ W2)
{
    mma_body<128, 64, 16, 32, 32, 256, true>(blockIdx.x, g_agg1, W2, g_hw2h,
                                             NN, CDIM, HDIM);
}

extern "C" void kernel_launch(void* const* d_in, const int* in_sizes, int n_in,
                              void* d_out, int out_size)
{
    const float* x   = (const float*)d_in[0];
    // d_in[1] = masked_nodes (unused by the reference output)
    const int*   pos = (const int*)d_in[2];
    const int*   neg = (const int*)d_in[3];
    const int*   ei  = (const int*)d_in[4];
    const float* W1  = (const float*)d_in[5];
    const float* b1  = (const float*)d_in[6];
    const float* W2  = (const float*)d_in[7];
    const float* b2  = (const float*)d_in[8];
    float* out = (float*)d_out;

    const int E   = in_sizes[4] / 2;
    const int EPn = in_sizes[2] / 2;
    const int SE  = 2 * EPn;
    const int* src = ei;
    const int* dst = ei + E;

    // degree histogram ∥ output-tail zeroing
    k_pre<<<CB + ZB, 256>>>(dst, E, out, SE, out_size);

    // CSR scan+bin (148 blocks, grid barriers) ∥ gemm1 (782 tiles)
    k_mega<<<NCSR + GB1, 256>>>(x, W1, src, dst, E);

    k_gather1<<<(NN * 8 + 255) / 256, 256>>>(b1);

    k_gemm2<<<(NN + 127) / 128, 256>>>(W2);
    k_gather2<<<(NN * 4 + 255) / 256, 256>>>(b2);

    const int sb = (SE * 4 + 255) / 256;
    k_score<<<sb + ZD, 256>>>(pos, neg, EPn, SE, sb, out);
}

// round 15
// speedup vs baseline: 1.0529x; 1.0267x over previous
#include <cuda_runtime.h>
#include <cuda_fp16.h>

#define NN   100000
#define FIN  256
#define HDIM 128
#define CDIM 64
#define MAXE 1600000
#define NCSR 148                  // scan blocks (co-resident wave 1)
#define GB1  ((NN + 127) / 128)   // gemm1 tiles = 782
#define CB   391                  // histogram blocks in mega
#define ZB   128                  // tail-zero blocks in mega
#define ZD   ((NN + 255) / 256)   // deg-zero blocks appended to score

// Scratch (static device globals — allocation-free per harness rules)
__device__ int     g_degi[NN];              // zeroed at END of each call (k_score)
__device__ int     g_rowptr[NN + 1];
__device__ int     g_bsum[NCSR];
__device__ int     g_boff[NCSR];
__device__ int     g_cursor[NN];
__device__ int     g_esrc[MAXE];            // edge sources grouped by dst (CSR)
__device__ float   g_dis[NN];
__device__ __half2 g_hw1h[NN * HDIM / 2];   // fp16: (x@W1)[v]  (UNSCALED)
__device__ __half2 g_agg1h[NN * HDIM / 2];  // fp16: relu(layer-1 aggregate)
__device__ __half2 g_hw2h[NN * CDIM / 2];   // fp16: dis[v]*(agg1@W2)[v]
__device__ __half2 g_agg2h[NN * CDIM / 2];  // fp16: final h2
__device__ int     g_barc;                  // barrier arrive counter
__device__ int     g_barg;                  // barrier generation

__device__ __forceinline__ void cp_async16(void* smem, const void* gmem) {
    unsigned s = (unsigned)__cvta_generic_to_shared(smem);
    asm volatile("cp.async.ca.shared.global [%0], [%1], 16;\n" :: "r"(s), "l"(gmem));
}
__device__ __forceinline__ void cp_commit() { asm volatile("cp.async.commit_group;\n"); }
__device__ __forceinline__ void cp_wait0()  { asm volatile("cp.async.wait_group 0;\n" ::: "memory"); }

__device__ __forceinline__ unsigned f2tf32(float f) {
    unsigned u;
    asm("cvt.rna.tf32.f32 %0, %1;\n" : "=r"(u) : "f"(f));
    return u;
}

__device__ __forceinline__ void mma_tf32(float* d, const unsigned* a, const unsigned* b) {
    asm volatile(
        "mma.sync.aligned.m16n8k8.row.col.f32.tf32.tf32.f32 "
        "{%0,%1,%2,%3}, {%4,%5,%6,%7}, {%8,%9}, {%0,%1,%2,%3};\n"
        : "+f"(d[0]), "+f"(d[1]), "+f"(d[2]), "+f"(d[3])
        : "r"(a[0]), "r"(a[1]), "r"(a[2]), "r"(a[3]), "r"(b[0]), "r"(b[1]));
}

__device__ __forceinline__ void u4_to_f8(uint4 u, float* f) {
    float2 t;
    t = __half22float2(*(__half2*)&u.x); f[0] = t.x; f[1] = t.y;
    t = __half22float2(*(__half2*)&u.y); f[2] = t.x; f[3] = t.y;
    t = __half22float2(*(__half2*)&u.z); f[4] = t.x; f[5] = t.y;
    t = __half22float2(*(__half2*)&u.w); f[6] = t.x; f[7] = t.y;
}

// Grid barrier among NCSR co-resident blocks.
__device__ __forceinline__ void csr_barrier() {
    __syncthreads();
    if (threadIdx.x == 0) {
        int gen = atomicAdd(&g_barg, 0);
        __threadfence();
        int t = atomicAdd(&g_barc, 1);
        if (t == NCSR - 1) {
            atomicExch(&g_barc, 0);
            __threadfence();
            atomicAdd(&g_barg, 1);
        } else {
            while (atomicAdd(&g_barg, 0) == gen) { __nanosleep(64); }
        }
    }
    __syncthreads();
}

// ───────────────── TF32 GEMM body, fp32 A via cp.async (gemm1 / R11 form) ──────
template<int BM, int BN, int BK, int WM, int WN, int NT>
__device__ __forceinline__ void mma_body_f32(
    int bx, const float* __restrict__ A, const float* __restrict__ Bg,
    __half2* __restrict__ C, int M, int N, int K)
{
    constexpr int BKp = BK + 4;
    constexpr int BNp = BN + 8;
    __shared__ float As[2][BM][BKp];
    __shared__ float Bs[2][BK][BNp];

    const int tid  = threadIdx.x;
    const int wid  = tid >> 5;
    const int lane = tid & 31;
    const int grp  = lane >> 2;
    const int qi   = lane & 3;
    constexpr int NWN = BN / WN;
    const int warp_m = wid / NWN;
    const int warp_n = wid % NWN;
    constexpr int MF = WM / 16;
    constexpr int NF = WN / 8;

    const int brow = bx * BM;

    float acc[MF][NF][4];
    #pragma unroll
    for (int i = 0; i < MF; i++)
        #pragma unroll
        for (int j = 0; j < NF; j++)
            #pragma unroll
            for (int q = 0; q < 4; q++) acc[i][j][q] = 0.0f;

    constexpr int AIT = (BM * BK / 4) / NT;
    constexpr int BIT = (BK * BN / 4) / NT;

    auto cpA = [&](int buf, int k0) {
        #pragma unroll
        for (int it = 0; it < AIT; it++) {
            int idx  = tid + it * NT;
            int row  = idx / (BK / 4);
            int kc   = (idx % (BK / 4)) * 4;
            int grow = brow + row;
            if (grow > M - 1) grow = M - 1;
            cp_async16(&As[buf][row][kc], A + (long long)grow * K + k0 + kc);
        }
    };
    auto cpB = [&](int buf, int k0) {
        #pragma unroll
        for (int it = 0; it < BIT; it++) {
            int idx = tid + it * NT;
            int kk  = idx / (BN / 4);
            int nc  = (idx % (BN / 4)) * 4;
            cp_async16(&Bs[buf][kk][nc], Bg + (long long)(k0 + kk) * N + nc);
        }
    };
    auto compute = [&](int buf) {
        #pragma unroll
        for (int ks = 0; ks < BK / 8; ks++) {
            int kk = ks * 8;
            unsigned a[MF][4], b[NF][2];
            #pragma unroll
            for (int fm = 0; fm < MF; fm++) {
                const float* ap = &As[buf][warp_m * WM + fm * 16 + grp][kk + qi];
                a[fm][0] = f2tf32(ap[0]);
                a[fm][1] = f2tf32(ap[8 * BKp]);
                a[fm][2] = f2tf32(ap[4]);
                a[fm][3] = f2tf32(ap[8 * BKp + 4]);
            }
            #pragma unroll
            for (int fn = 0; fn < NF; fn++) {
                const float* bp = &Bs[buf][kk + qi][warp_n * WN + fn * 8 + grp];
                b[fn][0] = f2tf32(bp[0]);
                b[fn][1] = f2tf32(bp[4 * BNp]);
            }
            #pragma unroll
            for (int fm = 0; fm < MF; fm++)
                #pragma unroll
                for (int fn = 0; fn < NF; fn++)
                    mma_tf32(acc[fm][fn], a[fm], b[fn]);
        }
    };

    cpA(0, 0); cpB(0, 0); cp_commit();
    cp_wait0(); __syncthreads();

    const int KT = K / BK;
    for (int t = 1; t < KT; t++) {
        cpA(t & 1, t * BK); cpB(t & 1, t * BK); cp_commit();
        compute((t - 1) & 1);
        cp_wait0(); __syncthreads();
    }
    compute((KT - 1) & 1);

    // Epilogue: UNSCALED fp16 store (gemm1 output; dis applied in gather1).
    #pragma unroll
    for (int fm = 0; fm < MF; fm++) {
        int r0 = brow + warp_m * WM + fm * 16 + grp;
        int r1 = r0 + 8;
        #pragma unroll
        for (int fn = 0; fn < NF; fn++) {
            int col = warp_n * WN + fn * 8 + 2 * qi;
            if (r0 < M)
                C[((long long)r0 * N + col) >> 1] =
                    __floats2half2_rn(acc[fm][fn][0], acc[fm][fn][1]);
            if (r1 < M)
                C[((long long)r1 * N + col) >> 1] =
                    __floats2half2_rn(acc[fm][fn][2], acc[fm][fn][3]);
        }
    }
}

// ───────────────────────── mega: gemm1 ∥ histogram ∥ tail-zero (R11) ───────────
__global__ void __launch_bounds__(256)
k_mega(const float* __restrict__ x, const float* __restrict__ W1,
       const int* __restrict__ dst, int E,
       float* __restrict__ out, int SE, int total)
{
    int bx = blockIdx.x;
    if (bx < GB1) {
        mma_body_f32<128, 128, 16, 64, 32, 256>(bx, x, W1, g_hw1h, NN, HDIM, FIN);
        return;
    }
    bx -= GB1;
    if (bx < CB) {
        for (int e = bx * 256 + threadIdx.x; e < E; e += CB * 256)
            atomicAdd(&g_degi[dst[e]], 1);
        return;
    }
    bx -= CB;
    for (int i = SE + bx * 256 + threadIdx.x; i < total; i += ZB * 256)
        out[i] = 0.0f;
}

// ───────────────────────── fused 3-phase scan (R11) ─────────────────────────
__global__ void __launch_bounds__(256)
k_scan(int E)
{
    const int c   = blockIdx.x;
    const int tid = threadIdx.x;
    __shared__ int sc[256];
    const int chunk = (NN + NCSR - 1) / NCSR;
    const int lo = c * chunk;
    const int hi = (lo + chunk < NN) ? lo + chunk : NN;

    {
        int s = 0;
        for (int i = lo + tid; i < hi; i += 256) s += g_degi[i];
        sc[tid] = s; __syncthreads();
        #pragma unroll
        for (int o = 128; o; o >>= 1) {
            if (tid < o) sc[tid] += sc[tid + o];
            __syncthreads();
        }
        if (tid == 0) g_bsum[c] = sc[0];
    }
    csr_barrier();

    if (c == 0) {
        int v = (tid < NCSR) ? g_bsum[tid] : 0;
        sc[tid] = v; __syncthreads();
        #pragma unroll
        for (int o = 1; o < 256; o <<= 1) {
            int t2 = (tid >= o) ? sc[tid - o] : 0;
            __syncthreads();
            sc[tid] += t2;
            __syncthreads();
        }
        if (tid < NCSR) g_boff[tid] = sc[tid] - v;
    }
    csr_barrier();

    {
        int running = g_boff[c];
        for (int base = lo; base < hi; base += 256) {
            int i = base + tid;
            int d = (i < hi) ? g_degi[i] : 0;
            sc[tid] = d; __syncthreads();
            #pragma unroll
            for (int o = 1; o < 256; o <<= 1) {
                int t2 = (tid >= o) ? sc[tid - o] : 0;
                __syncthreads();
                sc[tid] += t2;
                __syncthreads();
            }
            if (i < hi) {
                int r = running + sc[tid] - d;
                g_rowptr[i] = r;
                g_cursor[i] = r;
                g_dis[i]    = rsqrtf((float)d + 1.0f);
            }
            running += sc[255];
            __syncthreads();
        }
        if (c == 0 && tid == 0) g_rowptr[NN] = E;
    }
}

__global__ void k_bin(const int* __restrict__ src, const int* __restrict__ dst, int E) {
    int e = blockIdx.x * blockDim.x + threadIdx.x;
    if (e >= E) return;
    int d = dst[e];
    int p = atomicAdd(&g_cursor[d], 1);
    g_esrc[p] = src[e];
}

// ─────── gather1: 16 lanes/node, occ-8, 2-edge unroll, fp16 output (agg1h) ─────
// hw1h UNSCALED.  S = dv*h1[v] + Σ_e ds*h1[s];  agg1 = relu(dv*S + b1) as fp16.
__global__ void __launch_bounds__(256, 8)
k_gather1(const float* __restrict__ b1) {
    int t = blockIdx.x * blockDim.x + threadIdx.x;
    int v = t >> 4, lane = t & 15;
    if (v >= NN) return;
    int beg = g_rowptr[v], end = g_rowptr[v + 1];
    float dv = g_dis[v];
    const uint4* hw = (const uint4*)g_hw1h;   // 16 uint4 per row

    float a[8];
    {
        float f[8];
        u4_to_f8(hw[(long long)v * 16 + lane], f);
        #pragma unroll
        for (int i = 0; i < 8; i++) a[i] = dv * f[i];
    }

    int p = beg;
    for (; p + 1 < end; p += 2) {
        int s0 = __ldg(&g_esrc[p]);
        int s1 = __ldg(&g_esrc[p + 1]);
        float d0 = g_dis[s0], d1 = g_dis[s1];
        uint4 u0 = hw[(long long)s0 * 16 + lane];
        uint4 u1 = hw[(long long)s1 * 16 + lane];
        float f0[8], f1[8];
        u4_to_f8(u0, f0); u4_to_f8(u1, f1);
        #pragma unroll
        for (int i = 0; i < 8; i++) a[i] = fmaf(d0, f0[i], a[i]);
        #pragma unroll
        for (int i = 0; i < 8; i++) a[i] = fmaf(d1, f1[i], a[i]);
    }
    if (p < end) {
        int s0 = __ldg(&g_esrc[p]);
        float d0 = g_dis[s0];
        float f0[8];
        u4_to_f8(hw[(long long)s0 * 16 + lane], f0);
        #pragma unroll
        for (int i = 0; i < 8; i++) a[i] = fmaf(d0, f0[i], a[i]);
    }
    float4 c0 = ((const float4*)b1)[lane * 2];
    float4 c1 = ((const float4*)b1)[lane * 2 + 1];
    uint4 u;
    *(__half2*)&u.x = __floats2half2_rn(fmaxf(fmaf(dv, a[0], c0.x), 0.f),
                                        fmaxf(fmaf(dv, a[1], c0.y), 0.f));
    *(__half2*)&u.y = __floats2half2_rn(fmaxf(fmaf(dv, a[2], c0.z), 0.f),
                                        fmaxf(fmaf(dv, a[3], c0.w), 0.f));
    *(__half2*)&u.z = __floats2half2_rn(fmaxf(fmaf(dv, a[4], c1.x), 0.f),
                                        fmaxf(fmaf(dv, a[5], c1.y), 0.f));
    *(__half2*)&u.w = __floats2half2_rn(fmaxf(fmaf(dv, a[6], c1.z), 0.f),
                                        fmaxf(fmaf(dv, a[7], c1.w), 0.f));
    ((uint4*)g_agg1h)[(long long)v * 16 + lane] = u;
}

// ─────────── gemm2: fp16 A (register-staged LDG→cvt→STS), fp32 B (cp.async) ─────
// C = fp16(dis[row] * (relu(agg1) @ W2)).
__global__ void __launch_bounds__(256)
k_gemm2(const float* __restrict__ W2)
{
    constexpr int BM = 128, BN = 64, BK = 16, WM = 32, WN = 32;
    constexpr int BKp = BK + 4;
    constexpr int BNp = BN + 8;
    __shared__ float As[2][BM][BKp];
    __shared__ float Bs[2][BK][BNp];

    const int tid  = threadIdx.x;
    const int wid  = tid >> 5;
    const int lane = tid & 31;
    const int grp  = lane >> 2;
    const int qi   = lane & 3;
    constexpr int NWN = BN / WN;          // 2
    const int warp_m = wid / NWN;
    const int warp_n = wid % NWN;
    constexpr int MF = WM / 16;           // 2
    constexpr int NF = WN / 8;            // 4

    const int brow = blockIdx.x * BM;
    const __half* Ah = (const __half*)g_agg1h;

    float acc[MF][NF][4];
    #pragma unroll
    for (int i = 0; i < MF; i++)
        #pragma unroll
        for (int j = 0; j < NF; j++)
            #pragma unroll
            for (int q = 0; q < 4; q++) acc[i][j][q] = 0.0f;

    // A: each thread owns one 16B load (8 halves) per tile: 256 thr = 128 rows x 2.
    const int arow = tid >> 1;
    const int akc  = (tid & 1) * 8;
    uint4 areg;

    auto ldgA = [&](int k0) {
        int grow = brow + arow;
        if (grow > NN - 1) grow = NN - 1;
        areg = *(const uint4*)(Ah + (long long)grow * HDIM + k0 + akc);
    };
    auto stsA = [&](int buf) {
        const __half2* h = (const __half2*)&areg;
        #pragma unroll
        for (int i = 0; i < 4; i++) {
            float2 f = __half22float2(h[i]);
            As[buf][arow][akc + 2 * i]     = f.x;
            As[buf][arow][akc + 2 * i + 1] = f.y;
        }
    };
    auto cpB = [&](int buf, int k0) {
        int kk = tid / (BN / 4);          // 0..15
        int nc = (tid % (BN / 4)) * 4;
        cp_async16(&Bs[buf][kk][nc], W2 + (long long)(k0 + kk) * CDIM + nc);
        cp_commit();
    };
    auto compute = [&](int buf) {
        #pragma unroll
        for (int ks = 0; ks < BK / 8; ks++) {
            int kk = ks * 8;
            unsigned a[MF][4], b[NF][2];
            #pragma unroll
            for (int fm = 0; fm < MF; fm++) {
                const float* ap = &As[buf][warp_m * WM + fm * 16 + grp][kk + qi];
                a[fm][0] = f2tf32(ap[0]);
                a[fm][1] = f2tf32(ap[8 * BKp]);
                a[fm][2] = f2tf32(ap[4]);
                a[fm][3] = f2tf32(ap[8 * BKp + 4]);
            }
            #pragma unroll
            for (int fn = 0; fn < NF; fn++) {
                const float* bp = &Bs[buf][kk + qi][warp_n * WN + fn * 8 + grp];
                b[fn][0] = f2tf32(bp[0]);
                b[fn][1] = f2tf32(bp[4 * BNp]);
            }
            #pragma unroll
            for (int fm = 0; fm < MF; fm++)
                #pragma unroll
                for (int fn = 0; fn < NF; fn++)
                    mma_tf32(acc[fm][fn], a[fm], b[fn]);
        }
    };

    ldgA(0); cpB(0, 0);
    stsA(0);
    cp_wait0(); __syncthreads();

    const int KT = HDIM / BK;   // 8
    for (int t = 1; t < KT; t++) {
        ldgA(t * BK); cpB(t & 1, t * BK);
        compute((t - 1) & 1);
        stsA(t & 1);
        cp_wait0(); __syncthreads();
    }
    compute((KT - 1) & 1);

    #pragma unroll
    for (int fm = 0; fm < MF; fm++) {
        int r0 = brow + warp_m * WM + fm * 16 + grp;
        int r1 = r0 + 8;
        float d0 = (r0 < NN) ? g_dis[r0] : 0.0f;
        float d1 = (r1 < NN) ? g_dis[r1] : 0.0f;
        #pragma unroll
        for (int fn = 0; fn < NF; fn++) {
            int col = warp_n * WN + fn * 8 + 2 * qi;
            if (r0 < NN)
                g_hw2h[((long long)r0 * CDIM + col) >> 1] =
                    __floats2half2_rn(acc[fm][fn][0] * d0, acc[fm][fn][1] * d0);
            if (r1 < NN)
                g_hw2h[((long long)r1 * CDIM + col) >> 1] =
                    __floats2half2_rn(acc[fm][fn][2] * d1, acc[fm][fn][3] * d1);
        }
    }
}

// ───────── gather2: 4 lanes/node, 2 uint4 per lane (R11 measured-best) ─────────
__global__ void k_gather2(const float* __restrict__ b2) {
    int t = blockIdx.x * blockDim.x + threadIdx.x;
    int v = t >> 2, lane = t & 3;
    if (v >= NN) return;
    int beg = g_rowptr[v], end = g_rowptr[v + 1];
    float dv = g_dis[v];
    const uint4* hw = (const uint4*)g_hw2h;   // 8 uint4 per row

    float a[16];
    {
        uint4 u0 = hw[(long long)v * 8 + lane];
        uint4 u1 = hw[(long long)v * 8 + lane + 4];
        float f0[8], f1[8];
        u4_to_f8(u0, f0); u4_to_f8(u1, f1);
        #pragma unroll
        for (int i = 0; i < 8; i++) { a[i] = f0[i]; a[8 + i] = f1[i]; }
    }

    int p = beg;
    for (; p + 1 < end; p += 2) {
        int s0 = __ldg(&g_esrc[p]);
        int s1 = __ldg(&g_esrc[p + 1]);
        uint4 u00 = hw[(long long)s0 * 8 + lane];
        uint4 u01 = hw[(long long)s0 * 8 + lane + 4];
        uint4 u10 = hw[(long long)s1 * 8 + lane];
        uint4 u11 = hw[(long long)s1 * 8 + lane + 4];
        float f00[8], f01[8], f10[8], f11[8];
        u4_to_f8(u00, f00); u4_to_f8(u01, f01);
        u4_to_f8(u10, f10); u4_to_f8(u11, f11);
        #pragma unroll
        for (int i = 0; i < 8; i++) {
            a[i]     += f00[i] + f10[i];
            a[8 + i] += f01[i] + f11[i];
        }
    }
    if (p < end) {
        int s0 = __ldg(&g_esrc[p]);
        uint4 u00 = hw[(long long)s0 * 8 + lane];
        uint4 u01 = hw[(long long)s0 * 8 + lane + 4];
        float f00[8], f01[8];
        u4_to_f8(u00, f00); u4_to_f8(u01, f01);
        #pragma unroll
        for (int i = 0; i < 8; i++) { a[i] += f00[i]; a[8 + i] += f01[i]; }
    }

    const float4* bb = (const float4*)b2;
    #pragma unroll
    for (int h = 0; h < 2; h++) {
        float4 c0 = bb[h * 8 + lane * 2];
        float4 c1 = bb[h * 8 + lane * 2 + 1];
        float o0 = fmaf(dv, a[h*8+0], c0.x);
        float o1 = fmaf(dv, a[h*8+1], c0.y);
        float o2 = fmaf(dv, a[h*8+2], c0.z);
        float o3 = fmaf(dv, a[h*8+3], c0.w);
        float o4 = fmaf(dv, a[h*8+4], c1.x);
        float o5 = fmaf(dv, a[h*8+5], c1.y);
        float o6 = fmaf(dv, a[h*8+6], c1.z);
        float o7 = fmaf(dv, a[h*8+7], c1.w);
        uint4 u;
        *(__half2*)&u.x = __floats2half2_rn(o0, o1);
        *(__half2*)&u.y = __floats2half2_rn(o2, o3);
        *(__half2*)&u.z = __floats2half2_rn(o4, o5);
        *(__half2*)&u.w = __floats2half2_rn(o6, o7);
        ((uint4*)g_agg2h)[(long long)v * 8 + h * 4 + lane] = u;
    }
}

// ──────── scoring (4 lanes/edge, 2 uint4 per side) + restore g_degi=0 ────────
__global__ void k_score(const int* __restrict__ pos, const int* __restrict__ neg,
                        int EPn, int SE, int sb, float* __restrict__ out)
{
    if ((int)blockIdx.x >= sb) {   // tail blocks: re-zero degree histogram
        int i = (blockIdx.x - sb) * 256 + threadIdx.x;
        if (i < NN) g_degi[i] = 0;
        return;
    }
    int t = blockIdx.x * blockDim.x + threadIdx.x;
    int e = t >> 2, lane = t & 3;
    if (e >= SE) return;
    int i, j;
    if (e < EPn) { j = pos[e];       i = pos[e + EPn]; }
    else         { j = neg[e - EPn]; i = neg[e];       }
    const uint4* h4 = (const uint4*)g_agg2h;
    uint4 ua0 = h4[(long long)i * 8 + lane];
    uint4 ua1 = h4[(long long)i * 8 + lane + 4];
    uint4 ub0 = h4[(long long)j * 8 + lane];
    uint4 ub1 = h4[(long long)j * 8 + lane + 4];
    float fa0[8], fa1[8], fb0[8], fb1[8];
    u4_to_f8(ua0, fa0); u4_to_f8(ua1, fa1);
    u4_to_f8(ub0, fb0); u4_to_f8(ub1, fb1);
    float s = 0.f;
    #pragma unroll
    for (int q = 0; q < 8; q++) s = fmaf(fa0[q], fb0[q], s);
    #pragma unroll
    for (int q = 0; q < 8; q++) s = fmaf(fa1[q], fb1[q], s);
    s += __shfl_xor_sync(0xffffffffu, s, 2);
    s += __shfl_xor_sync(0xffffffffu, s, 1);
    if (lane == 0) out[e] = s;
}

extern "C" void kernel_launch(void* const* d_in, const int* in_sizes, int n_in,
                              void* d_out, int out_size)
{
    const float* x   = (const float*)d_in[0];
    // d_in[1] = masked_nodes (unused by the reference output)
    const int*   pos = (const int*)d_in[2];
    const int*   neg = (const int*)d_in[3];
    const int*   ei  = (const int*)d_in[4];
    const float* W1  = (const float*)d_in[5];
    const float* b1  = (const float*)d_in[6];
    const float* W2  = (const float*)d_in[7];
    const float* b2  = (const float*)d_in[8];
    float* out = (float*)d_out;

    const int E   = in_sizes[4] / 2;
    const int EPn = in_sizes[2] / 2;
    const int SE  = 2 * EPn;
    const int* src = ei;
    const int* dst = ei + E;

    // gemm1 ∥ degree histogram ∥ output-tail zeroing
    k_mega<<<GB1 + CB + ZB, 256>>>(x, W1, dst, E, out, SE, out_size);

    // fused 3-phase prefix scan (rowptr/cursor/dis)
    k_scan<<<NCSR, 256>>>(E);
    k_bin <<<(E + 255) / 256, 256>>>(src, dst, E);

    k_gather1<<<(NN * 16 + 255) / 256, 256>>>(b1);

    k_gemm2<<<(NN + 127) / 128, 256>>>(W2);
    k_gather2<<<(NN * 4 + 255) / 256, 256>>>(b2);

    const int sb = (SE * 4 + 255) / 256;
    k_score<<<sb + ZD, 256>>>(pos, neg, EPn, SE, sb, out);
}

// round 16
// speedup vs baseline: 1.0975x; 1.0424x over previous
#include <cuda_runtime.h>
#include <cuda_fp16.h>

#define NN   100000
#define FIN  256
#define HDIM 128
#define CDIM 64
#define MAXE 1600000
#define NCSR 148                  // scan blocks (co-resident wave 1)
#define GB1  ((NN + 127) / 128)   // gemm1 tiles = 782
#define CB   391                  // histogram blocks in mega
#define ZB   128                  // tail-zero blocks in mega
#define ZD   ((NN + 255) / 256)   // deg-zero blocks appended to score

// Scratch (static device globals — allocation-free per harness rules)
__device__ int     g_degi[NN];              // zeroed at END of each call (k_score)
__device__ int     g_rowptr[NN + 1];
__device__ int     g_bsum[NCSR];
__device__ int     g_boff[NCSR];
__device__ int     g_cursor[NN];
__device__ int     g_esrc[MAXE];            // edge sources grouped by dst (CSR)
__device__ float   g_dis[NN];
__device__ __half2 g_hw1h[NN * HDIM / 2];   // fp16: (x@W1)[v]  (UNSCALED)
__device__ __half2 g_agg1h[NN * HDIM / 2];  // fp16: relu(layer-1 aggregate)
__device__ __half2 g_hw2h[NN * CDIM / 2];   // fp16: dis[v]*(agg1@W2)[v]
__device__ __half2 g_agg2h[NN * CDIM / 2];  // fp16: final h2
__device__ int     g_barc;                  // barrier arrive counter
__device__ int     g_barg;                  // barrier generation

__device__ __forceinline__ void cp_async16(void* smem, const void* gmem) {
    unsigned s = (unsigned)__cvta_generic_to_shared(smem);
    asm volatile("cp.async.ca.shared.global [%0], [%1], 16;\n" :: "r"(s), "l"(gmem));
}
__device__ __forceinline__ void cp_commit() { asm volatile("cp.async.commit_group;\n"); }
__device__ __forceinline__ void cp_wait0()  { asm volatile("cp.async.wait_group 0;\n" ::: "memory"); }

// fp16 tensor-core mma: D(f32) += A(f16,row) * B(f16,col), m16n8k16
__device__ __forceinline__ void mma_f16(float* d, const unsigned* a, const unsigned* b) {
    asm volatile(
        "mma.sync.aligned.m16n8k16.row.col.f32.f16.f16.f32 "
        "{%0,%1,%2,%3}, {%4,%5,%6,%7}, {%8,%9}, {%0,%1,%2,%3};\n"
        : "+f"(d[0]), "+f"(d[1]), "+f"(d[2]), "+f"(d[3])
        : "r"(a[0]), "r"(a[1]), "r"(a[2]), "r"(a[3]), "r"(b[0]), "r"(b[1]));
}

__device__ __forceinline__ void u4_to_f8(uint4 u, float* f) {
    float2 t;
    t = __half22float2(*(__half2*)&u.x); f[0] = t.x; f[1] = t.y;
    t = __half22float2(*(__half2*)&u.y); f[2] = t.x; f[3] = t.y;
    t = __half22float2(*(__half2*)&u.z); f[4] = t.x; f[5] = t.y;
    t = __half22float2(*(__half2*)&u.w); f[6] = t.x; f[7] = t.y;
}

// Grid barrier among NCSR co-resident blocks.
__device__ __forceinline__ void csr_barrier() {
    __syncthreads();
    if (threadIdx.x == 0) {
        int gen = atomicAdd(&g_barg, 0);
        __threadfence();
        int t = atomicAdd(&g_barc, 1);
        if (t == NCSR - 1) {
            atomicExch(&g_barc, 0);
            __threadfence();
            atomicAdd(&g_barg, 1);
        } else {
            while (atomicAdd(&g_barg, 0) == gen) { __nanosleep(64); }
        }
    }
    __syncthreads();
}

// ───────────── gemm1: fp16 m16n8k16, fp32 inputs staged to fp16 smem ───────────
// hw1h = fp16(x @ W1), unscaled.  BM=128 BN=128 BK=16, 8 warps, warp 64x32.
__device__ __forceinline__ void gemm1_body(
    int bx, const float* __restrict__ x, const float* __restrict__ W1)
{
    constexpr int BM = 128, BN = 128, BK = 16;
    constexpr int BKA = BK + 8;               // halves per row (48B stride)
    __shared__ __half As[2][BM][BKA];
    __shared__ __half Bs[2][BN][BKA];         // n-major: Bs[n][k]

    const int tid  = threadIdx.x;
    const int wid  = tid >> 5;
    const int lane = tid & 31;
    const int grp  = lane >> 2;
    const int qi   = lane & 3;
    const int warp_m = wid >> 2;              // 0..1  (WM=64)
    const int warp_n = wid & 3;               // 0..3  (WN=32)
    const int brow = bx * BM;

    float acc[4][4][4];
    #pragma unroll
    for (int i = 0; i < 4; i++)
        #pragma unroll
        for (int j = 0; j < 4; j++)
            #pragma unroll
            for (int q = 0; q < 4; q++) acc[i][j][q] = 0.0f;

    // A staging: 2 float4 per thread per tile.
    const int ar0 = tid >> 2, ak0 = (tid & 3) * 4;       // rows 0..63
    const int ar1 = (tid + 256) >> 2;                     // rows 64..127
    float4 areg0, areg1;
    // B staging: n = tid&127, kb = (tid>>7)*8, 8 scalar loads.
    const int bn = tid & 127, bkb = (tid >> 7) * 8;
    float bv[8];

    auto ldgA = [&](int k0) {
        int r0 = brow + ar0; if (r0 > NN - 1) r0 = NN - 1;
        int r1 = brow + ar1; if (r1 > NN - 1) r1 = NN - 1;
        areg0 = *(const float4*)(x + (long long)r0 * FIN + k0 + ak0);
        areg1 = *(const float4*)(x + (long long)r1 * FIN + k0 + ak0);
    };
    auto ldgB = [&](int k0) {
        #pragma unroll
        for (int i = 0; i < 8; i++)
            bv[i] = W1[(long long)(k0 + bkb + i) * HDIM + bn];
    };
    auto stsA = [&](int buf) {
        uint2 u0, u1;
        *(__half2*)&u0.x = __floats2half2_rn(areg0.x, areg0.y);
        *(__half2*)&u0.y = __floats2half2_rn(areg0.z, areg0.w);
        *(__half2*)&u1.x = __floats2half2_rn(areg1.x, areg1.y);
        *(__half2*)&u1.y = __floats2half2_rn(areg1.z, areg1.w);
        *(uint2*)&As[buf][ar0][ak0] = u0;
        *(uint2*)&As[buf][ar1][ak0] = u1;
    };
    auto stsB = [&](int buf) {
        uint4 u;
        *(__half2*)&u.x = __floats2half2_rn(bv[0], bv[1]);
        *(__half2*)&u.y = __floats2half2_rn(bv[2], bv[3]);
        *(__half2*)&u.z = __floats2half2_rn(bv[4], bv[5]);
        *(__half2*)&u.w = __floats2half2_rn(bv[6], bv[7]);
        *(uint4*)&Bs[buf][bn][bkb] = u;
    };
    auto compute = [&](int buf) {
        unsigned a[4][4], b[4][2];
        #pragma unroll
        for (int fm = 0; fm < 4; fm++) {
            int row = warp_m * 64 + fm * 16 + grp;
            a[fm][0] = *(const unsigned*)&As[buf][row][2 * qi];
            a[fm][1] = *(const unsigned*)&As[buf][row + 8][2 * qi];
            a[fm][2] = *(const unsigned*)&As[buf][row][2 * qi + 8];
            a[fm][3] = *(const unsigned*)&As[buf][row + 8][2 * qi + 8];
        }
        #pragma unroll
        for (int fn = 0; fn < 4; fn++) {
            int n = warp_n * 32 + fn * 8 + grp;
            b[fn][0] = *(const unsigned*)&Bs[buf][n][2 * qi];
            b[fn][1] = *(const unsigned*)&Bs[buf][n][2 * qi + 8];
        }
        #pragma unroll
        for (int fm = 0; fm < 4; fm++)
            #pragma unroll
            for (int fn = 0; fn < 4; fn++)
                mma_f16(acc[fm][fn], a[fm], b[fn]);
    };

    ldgA(0); ldgB(0);
    stsA(0); stsB(0);
    __syncthreads();

    const int KT = FIN / BK;   // 16
    for (int t = 1; t < KT; t++) {
        ldgA(t * BK); ldgB(t * BK);
        compute((t - 1) & 1);
        stsA(t & 1); stsB(t & 1);
        __syncthreads();
    }
    compute((KT - 1) & 1);

    // Epilogue: UNSCALED fp16 store (dis applied in gather1).
    #pragma unroll
    for (int fm = 0; fm < 4; fm++) {
        int r0 = brow + warp_m * 64 + fm * 16 + grp;
        int r1 = r0 + 8;
        #pragma unroll
        for (int fn = 0; fn < 4; fn++) {
            int col = warp_n * 32 + fn * 8 + 2 * qi;
            if (r0 < NN)
                g_hw1h[((long long)r0 * HDIM + col) >> 1] =
                    __floats2half2_rn(acc[fm][fn][0], acc[fm][fn][1]);
            if (r1 < NN)
                g_hw1h[((long long)r1 * HDIM + col) >> 1] =
                    __floats2half2_rn(acc[fm][fn][2], acc[fm][fn][3]);
        }
    }
}

// ───────────────────────── mega: gemm1 ∥ histogram ∥ tail-zero ─────────────────
__global__ void __launch_bounds__(256)
k_mega(const float* __restrict__ x, const float* __restrict__ W1,
       const int* __restrict__ dst, int E,
       float* __restrict__ out, int SE, int total)
{
    int bx = blockIdx.x;
    if (bx < GB1) {
        gemm1_body(bx, x, W1);
        return;
    }
    bx -= GB1;
    if (bx < CB) {
        for (int e = bx * 256 + threadIdx.x; e < E; e += CB * 256)
            atomicAdd(&g_degi[dst[e]], 1);
        return;
    }
    bx -= CB;
    for (int i = SE + bx * 256 + threadIdx.x; i < total; i += ZB * 256)
        out[i] = 0.0f;
}

// ───────────────────────── fused 3-phase scan (R11) ─────────────────────────
__global__ void __launch_bounds__(256)
k_scan(int E)
{
    const int c   = blockIdx.x;
    const int tid = threadIdx.x;
    __shared__ int sc[256];
    const int chunk = (NN + NCSR - 1) / NCSR;
    const int lo = c * chunk;
    const int hi = (lo + chunk < NN) ? lo + chunk : NN;

    {
        int s = 0;
        for (int i = lo + tid; i < hi; i += 256) s += g_degi[i];
        sc[tid] = s; __syncthreads();
        #pragma unroll
        for (int o = 128; o; o >>= 1) {
            if (tid < o) sc[tid] += sc[tid + o];
            __syncthreads();
        }
        if (tid == 0) g_bsum[c] = sc[0];
    }
    csr_barrier();

    if (c == 0) {
        int v = (tid < NCSR) ? g_bsum[tid] : 0;
        sc[tid] = v; __syncthreads();
        #pragma unroll
        for (int o = 1; o < 256; o <<= 1) {
            int t2 = (tid >= o) ? sc[tid - o] : 0;
            __syncthreads();
            sc[tid] += t2;
            __syncthreads();
        }
        if (tid < NCSR) g_boff[tid] = sc[tid] - v;
    }
    csr_barrier();

    {
        int running = g_boff[c];
        for (int base = lo; base < hi; base += 256) {
            int i = base + tid;
            int d = (i < hi) ? g_degi[i] : 0;
            sc[tid] = d; __syncthreads();
            #pragma unroll
            for (int o = 1; o < 256; o <<= 1) {
                int t2 = (tid >= o) ? sc[tid - o] : 0;
                __syncthreads();
                sc[tid] += t2;
                __syncthreads();
            }
            if (i < hi) {
                int r = running + sc[tid] - d;
                g_rowptr[i] = r;
                g_cursor[i] = r;
                g_dis[i]    = rsqrtf((float)d + 1.0f);
            }
            running += sc[255];
            __syncthreads();
        }
        if (c == 0 && tid == 0) g_rowptr[NN] = E;
    }
}

__global__ void k_bin(const int* __restrict__ src, const int* __restrict__ dst, int E) {
    int e = blockIdx.x * blockDim.x + threadIdx.x;
    if (e >= E) return;
    int d = dst[e];
    int p = atomicAdd(&g_cursor[d], 1);
    g_esrc[p] = src[e];
}

// ─────── gather1: 16 lanes/node, occ-8, 2-edge unroll, fp16 output (R15) ───────
__global__ void __launch_bounds__(256, 8)
k_gather1(const float* __restrict__ b1) {
    int t = blockIdx.x * blockDim.x + threadIdx.x;
    int v = t >> 4, lane = t & 15;
    if (v >= NN) return;
    int beg = g_rowptr[v], end = g_rowptr[v + 1];
    float dv = g_dis[v];
    const uint4* hw = (const uint4*)g_hw1h;   // 16 uint4 per row

    float a[8];
    {
        float f[8];
        u4_to_f8(hw[(long long)v * 16 + lane], f);
        #pragma unroll
        for (int i = 0; i < 8; i++) a[i] = dv * f[i];
    }

    int p = beg;
    for (; p + 1 < end; p += 2) {
        int s0 = __ldg(&g_esrc[p]);
        int s1 = __ldg(&g_esrc[p + 1]);
        float d0 = g_dis[s0], d1 = g_dis[s1];
        uint4 u0 = hw[(long long)s0 * 16 + lane];
        uint4 u1 = hw[(long long)s1 * 16 + lane];
        float f0[8], f1[8];
        u4_to_f8(u0, f0); u4_to_f8(u1, f1);
        #pragma unroll
        for (int i = 0; i < 8; i++) a[i] = fmaf(d0, f0[i], a[i]);
        #pragma unroll
        for (int i = 0; i < 8; i++) a[i] = fmaf(d1, f1[i], a[i]);
    }
    if (p < end) {
        int s0 = __ldg(&g_esrc[p]);
        float d0 = g_dis[s0];
        float f0[8];
        u4_to_f8(hw[(long long)s0 * 16 + lane], f0);
        #pragma unroll
        for (int i = 0; i < 8; i++) a[i] = fmaf(d0, f0[i], a[i]);
    }
    float4 c0 = ((const float4*)b1)[lane * 2];
    float4 c1 = ((const float4*)b1)[lane * 2 + 1];
    uint4 u;
    *(__half2*)&u.x = __floats2half2_rn(fmaxf(fmaf(dv, a[0], c0.x), 0.f),
                                        fmaxf(fmaf(dv, a[1], c0.y), 0.f));
    *(__half2*)&u.y = __floats2half2_rn(fmaxf(fmaf(dv, a[2], c0.z), 0.f),
                                        fmaxf(fmaf(dv, a[3], c0.w), 0.f));
    *(__half2*)&u.z = __floats2half2_rn(fmaxf(fmaf(dv, a[4], c1.x), 0.f),
                                        fmaxf(fmaf(dv, a[5], c1.y), 0.f));
    *(__half2*)&u.w = __floats2half2_rn(fmaxf(fmaf(dv, a[6], c1.z), 0.f),
                                        fmaxf(fmaf(dv, a[7], c1.w), 0.f));
    ((uint4*)g_agg1h)[(long long)v * 16 + lane] = u;
}

// ───────── gemm2: fp16 m16n8k16, A = agg1h via direct cp.async (fp16) ──────────
// hw2h = fp16(dis[row] * (relu(agg1) @ W2)).  BM=128 BN=64 BK=16, warp 32x32.
__global__ void __launch_bounds__(256)
k_gemm2(const float* __restrict__ W2)
{
    constexpr int BM = 128, BN = 64, BK = 16;
    constexpr int BKA = BK + 8;
    __shared__ __half As[2][BM][BKA];
    __shared__ __half Bs[2][BN][BKA];

    const int tid  = threadIdx.x;
    const int wid  = tid >> 5;
    const int lane = tid & 31;
    const int grp  = lane >> 2;
    const int qi   = lane & 3;
    const int warp_m = wid >> 1;              // 0..3 (WM=32)
    const int warp_n = wid & 1;               // 0..1 (WN=32)
    const int brow = blockIdx.x * BM;
    const __half* Ah = (const __half*)g_agg1h;

    float acc[2][4][4];
    #pragma unroll
    for (int i = 0; i < 2; i++)
        #pragma unroll
        for (int j = 0; j < 4; j++)
            #pragma unroll
            for (int q = 0; q < 4; q++) acc[i][j][q] = 0.0f;

    // A: 1 cp.async chunk (8 halves) per thread per tile.
    const int arow = tid >> 1, akc = (tid & 1) * 8;
    // B: n = tid&63, kb = (tid>>6)*4, 4 scalar loads.
    const int bn = tid & 63, bkb = (tid >> 6) * 4;
    float bv[4];

    auto cpA = [&](int buf, int k0) {
        int grow = brow + arow; if (grow > NN - 1) grow = NN - 1;
        cp_async16(&As[buf][arow][akc], Ah + (long long)grow * HDIM + k0 + akc);
    };
    auto ldgB = [&](int k0) {
        #pragma unroll
        for (int i = 0; i < 4; i++)
            bv[i] = W2[(long long)(k0 + bkb + i) * CDIM + bn];
    };
    auto stsB = [&](int buf) {
        uint2 u;
        *(__half2*)&u.x = __floats2half2_rn(bv[0], bv[1]);
        *(__half2*)&u.y = __floats2half2_rn(bv[2], bv[3]);
        *(uint2*)&Bs[buf][bn][bkb] = u;
    };
    auto compute = [&](int buf) {
        unsigned a[2][4], b[4][2];
        #pragma unroll
        for (int fm = 0; fm < 2; fm++) {
            int row = warp_m * 32 + fm * 16 + grp;
            a[fm][0] = *(const unsigned*)&As[buf][row][2 * qi];
            a[fm][1] = *(const unsigned*)&As[buf][row + 8][2 * qi];
            a[fm][2] = *(const unsigned*)&As[buf][row][2 * qi + 8];
            a[fm][3] = *(const unsigned*)&As[buf][row + 8][2 * qi + 8];
        }
        #pragma unroll
        for (int fn = 0; fn < 4; fn++) {
            int n = warp_n * 32 + fn * 8 + grp;
            b[fn][0] = *(const unsigned*)&Bs[buf][n][2 * qi];
            b[fn][1] = *(const unsigned*)&Bs[buf][n][2 * qi + 8];
        }
        #pragma unroll
        for (int fm = 0; fm < 2; fm++)
            #pragma unroll
            for (int fn = 0; fn < 4; fn++)
                mma_f16(acc[fm][fn], a[fm], b[fn]);
    };

    cpA(0, 0); cp_commit();
    ldgB(0); stsB(0);
    cp_wait0(); __syncthreads();

    const int KT = HDIM / BK;   // 8
    for (int t = 1; t < KT; t++) {
        cpA(t & 1, t * BK); cp_commit();
        ldgB(t * BK);
        compute((t - 1) & 1);
        stsB(t & 1);
        cp_wait0(); __syncthreads();
    }
    compute((KT - 1) & 1);

    #pragma unroll
    for (int fm = 0; fm < 2; fm++) {
        int r0 = brow + warp_m * 32 + fm * 16 + grp;
        int r1 = r0 + 8;
        float d0 = (r0 < NN) ? g_dis[r0] : 0.0f;
        float d1 = (r1 < NN) ? g_dis[r1] : 0.0f;
        #pragma unroll
        for (int fn = 0; fn < 4; fn++) {
            int col = warp_n * 32 + fn * 8 + 2 * qi;
            if (r0 < NN)
                g_hw2h[((long long)r0 * CDIM + col) >> 1] =
                    __floats2half2_rn(acc[fm][fn][0] * d0, acc[fm][fn][1] * d0);
            if (r1 < NN)
                g_hw2h[((long long)r1 * CDIM + col) >> 1] =
                    __floats2half2_rn(acc[fm][fn][2] * d1, acc[fm][fn][3] * d1);
        }
    }
}

// ───────── gather2: 4 lanes/node, 2 uint4 per lane (R11 measured-best) ─────────
__global__ void k_gather2(const float* __restrict__ b2) {
    int t = blockIdx.x * blockDim.x + threadIdx.x;
    int v = t >> 2, lane = t & 3;
    if (v >= NN) return;
    int beg = g_rowptr[v], end = g_rowptr[v + 1];
    float dv = g_dis[v];
    const uint4* hw = (const uint4*)g_hw2h;   // 8 uint4 per row

    float a[16];
    {
        uint4 u0 = hw[(long long)v * 8 + lane];
        uint4 u1 = hw[(long long)v * 8 + lane + 4];
        float f0[8], f1[8];
        u4_to_f8(u0, f0); u4_to_f8(u1, f1);
        #pragma unroll
        for (int i = 0; i < 8; i++) { a[i] = f0[i]; a[8 + i] = f1[i]; }
    }

    int p = beg;
    for (; p + 1 < end; p += 2) {
        int s0 = __ldg(&g_esrc[p]);
        int s1 = __ldg(&g_esrc[p + 1]);
        uint4 u00 = hw[(long long)s0 * 8 + lane];
        uint4 u01 = hw[(long long)s0 * 8 + lane + 4];
        uint4 u10 = hw[(long long)s1 * 8 + lane];
        uint4 u11 = hw[(long long)s1 * 8 + lane + 4];
        float f00[8], f01[8], f10[8], f11[8];
        u4_to_f8(u00, f00); u4_to_f8(u01, f01);
        u4_to_f8(u10, f10); u4_to_f8(u11, f11);
        #pragma unroll
        for (int i = 0; i < 8; i++) {
            a[i]     += f00[i] + f10[i];
            a[8 + i] += f01[i] + f11[i];
        }
    }
    if (p < end) {
        int s0 = __ldg(&g_esrc[p]);
        uint4 u00 = hw[(long long)s0 * 8 + lane];
        uint4 u01 = hw[(long long)s0 * 8 + lane + 4];
        float f00[8], f01[8];
        u4_to_f8(u00, f00); u4_to_f8(u01, f01);
        #pragma unroll
        for (int i = 0; i < 8; i++) { a[i] += f00[i]; a[8 + i] += f01[i]; }
    }

    const float4* bb = (const float4*)b2;
    #pragma unroll
    for (int h = 0; h < 2; h++) {
        float4 c0 = bb[h * 8 + lane * 2];
        float4 c1 = bb[h * 8 + lane * 2 + 1];
        float o0 = fmaf(dv, a[h*8+0], c0.x);
        float o1 = fmaf(dv, a[h*8+1], c0.y);
        float o2 = fmaf(dv, a[h*8+2], c0.z);
        float o3 = fmaf(dv, a[h*8+3], c0.w);
        float o4 = fmaf(dv, a[h*8+4], c1.x);
        float o5 = fmaf(dv, a[h*8+5], c1.y);
        float o6 = fmaf(dv, a[h*8+6], c1.z);
        float o7 = fmaf(dv, a[h*8+7], c1.w);
        uint4 u;
        *(__half2*)&u.x = __floats2half2_rn(o0, o1);
        *(__half2*)&u.y = __floats2half2_rn(o2, o3);
        *(__half2*)&u.z = __floats2half2_rn(o4, o5);
        *(__half2*)&u.w = __floats2half2_rn(o6, o7);
        ((uint4*)g_agg2h)[(long long)v * 8 + h * 4 + lane] = u;
    }
}

// ──────── scoring (4 lanes/edge, 2 uint4 per side) + restore g_degi=0 ────────
__global__ void k_score(const int* __restrict__ pos, const int* __restrict__ neg,
                        int EPn, int SE, int sb, float* __restrict__ out)
{
    if ((int)blockIdx.x >= sb) {   // tail blocks: re-zero degree histogram
        int i = (blockIdx.x - sb) * 256 + threadIdx.x;
        if (i < NN) g_degi[i] = 0;
        return;
    }
    int t = blockIdx.x * blockDim.x + threadIdx.x;
    int e = t >> 2, lane = t & 3;
    if (e >= SE) return;
    int i, j;
    if (e < EPn) { j = pos[e];       i = pos[e + EPn]; }
    else         { j = neg[e - EPn]; i = neg[e];       }
    const uint4* h4 = (const uint4*)g_agg2h;
    uint4 ua0 = h4[(long long)i * 8 + lane];
    uint4 ua1 = h4[(long long)i * 8 + lane + 4];
    uint4 ub0 = h4[(long long)j * 8 + lane];
    uint4 ub1 = h4[(long long)j * 8 + lane + 4];
    float fa0[8], fa1[8], fb0[8], fb1[8];
    u4_to_f8(ua0, fa0); u4_to_f8(ua1, fa1);
    u4_to_f8(ub0, fb0); u4_to_f8(ub1, fb1);
    float s = 0.f;
    #pragma unroll
    for (int q = 0; q < 8; q++) s = fmaf(fa0[q], fb0[q], s);
    #pragma unroll
    for (int q = 0; q < 8; q++) s = fmaf(fa1[q], fb1[q], s);
    s += __shfl_xor_sync(0xffffffffu, s, 2);
    s += __shfl_xor_sync(0xffffffffu, s, 1);
    if (lane == 0) out[e] = s;
}

extern "C" void kernel_launch(void* const* d_in, const int* in_sizes, int n_in,
                              void* d_out, int out_size)
{
    const float* x   = (const float*)d_in[0];
    // d_in[1] = masked_nodes (unused by the reference output)
    const int*   pos = (const int*)d_in[2];
    const int*   neg = (const int*)d_in[3];
    const int*   ei  = (const int*)d_in[4];
    const float* W1  = (const float*)d_in[5];
    const float* b1  = (const float*)d_in[6];
    const float* W2  = (const float*)d_in[7];
    const float* b2  = (const float*)d_in[8];
    float* out = (float*)d_out;

    const int E   = in_sizes[4] / 2;
    const int EPn = in_sizes[2] / 2;
    const int SE  = 2 * EPn;
    const int* src = ei;
    const int* dst = ei + E;

    // gemm1 ∥ degree histogram ∥ output-tail zeroing
    k_mega<<<GB1 + CB + ZB, 256>>>(x, W1, dst, E, out, SE, out_size);

    // fused 3-phase prefix scan (rowptr/cursor/dis)
    k_scan<<<NCSR, 256>>>(E);
    k_bin <<<(E + 255) / 256, 256>>>(src, dst, E);

    k_gather1<<<(NN * 16 + 255) / 256, 256>>>(b1);

    k_gemm2<<<(NN + 127) / 128, 256>>>(W2);
    k_gather2<<<(NN * 4 + 255) / 256, 256>>>(b2);

    const int sb = (SE * 4 + 255) / 256;
    k_score<<<sb + ZD, 256>>>(pos, neg, EPn, SE, sb, out);
}